// round 5
// baseline (speedup 1.0000x reference)
#include <cuda_runtime.h>
#include <cuda_bf16.h>

#define IND   128
#define HID   64
#define HEADS 4
#define NEG   0.2f

#define NMAX  50000
#define EMAX  800000
#define FULLM 0xffffffffu

// ---------------- scratch (device globals; no allocation allowed) ----------
static __device__ int   g_cnt [NMAX];            // dst histogram
static __device__ int   g_offs[NMAX + 1];        // CSR row offsets
static __device__ int   g_cur [NMAX];            // fill cursors
static __device__ int   g_bsum[512];             // scan block sums
static __device__ int   g_csrc[EMAX];            // CSR src ids (grouped by dst)
static __device__ float g_dinv[NMAX];
static __device__ float g_xw  [NMAX * HID];      // x @ W_gcn
static __device__ __nv_bfloat16 g_hh[(NMAX + 64) * HID];  // h hi (padded rows)
static __device__ __nv_bfloat16 g_hl[(NMAX + 64) * HID];  // h lo
static __device__ __nv_bfloat16 g_wth[2 * 256 * HID];     // W^T hi: [mat][n][k]
static __device__ __nv_bfloat16 g_wtl[2 * 256 * HID];     // W^T lo
static __device__ float g_xl  [NMAX * HEADS * HID];
static __device__ float g_xr  [NMAX * HEADS * HID];

__device__ __forceinline__ float lrelu(float z) { return z > 0.f ? z : NEG * z; }

__device__ __forceinline__ void mma_bf16(float4& c, unsigned a0, unsigned a1,
                                         unsigned a2, unsigned a3,
                                         unsigned b0, unsigned b1) {
    asm volatile(
        "mma.sync.aligned.m16n8k16.row.col.f32.bf16.bf16.f32 "
        "{%0,%1,%2,%3}, {%4,%5,%6,%7}, {%8,%9}, {%0,%1,%2,%3};"
        : "+f"(c.x), "+f"(c.y), "+f"(c.z), "+f"(c.w)
        : "r"(a0), "r"(a1), "r"(a2), "r"(a3), "r"(b0), "r"(b1));
}

// ---------------- CSR build ----------------
__global__ void k_init(int n) {
    int i = blockIdx.x * blockDim.x + threadIdx.x;
    if (i < n) g_cnt[i] = 0;
}

__global__ void k_hist(const int* __restrict__ dst, int e) {
    int i = blockIdx.x * blockDim.x + threadIdx.x;
    if (i < e) atomicAdd(&g_cnt[dst[i]], 1);
}

__global__ void k_scan1(int n) {
    __shared__ int wsum[32];
    int i = blockIdx.x * 1024 + threadIdx.x;
    int v = (i < n) ? g_cnt[i] : 0;
    int lane = threadIdx.x & 31, wid = threadIdx.x >> 5;
    int x = v;
    #pragma unroll
    for (int o = 1; o < 32; o <<= 1) {
        int t = __shfl_up_sync(FULLM, x, o);
        if (lane >= o) x += t;
    }
    if (lane == 31) wsum[wid] = x;
    __syncthreads();
    if (wid == 0) {
        int s = wsum[lane];
        #pragma unroll
        for (int o = 1; o < 32; o <<= 1) {
            int t = __shfl_up_sync(FULLM, s, o);
            if (lane >= o) s += t;
        }
        wsum[lane] = s;
    }
    __syncthreads();
    int add = wid ? wsum[wid - 1] : 0;
    if (i < n) g_offs[i] = add + x - v;
    if (threadIdx.x == 1023) g_bsum[blockIdx.x] = wsum[31];
}

__global__ void k_scan2(int nblk) {
    __shared__ int sh[64];
    int v = (threadIdx.x < nblk) ? g_bsum[threadIdx.x] : 0;
    sh[threadIdx.x] = v;
    __syncthreads();
    #pragma unroll
    for (int o = 1; o < 64; o <<= 1) {
        int t = (threadIdx.x >= o) ? sh[threadIdx.x - o] : 0;
        __syncthreads();
        sh[threadIdx.x] += t;
        __syncthreads();
    }
    if (threadIdx.x < nblk) g_bsum[threadIdx.x] = sh[threadIdx.x] - v;
}

__global__ void k_scan3(int n, int e) {
    int i = blockIdx.x * blockDim.x + threadIdx.x;
    if (i < n) {
        int off = g_offs[i] + g_bsum[i >> 10];
        g_offs[i] = off;
        g_cur[i]  = off;
        g_dinv[i] = rsqrtf((float)g_cnt[i] + 1.0f);
    }
    if (i == 0) g_offs[n] = e;
}

__global__ void k_fill(const int* __restrict__ src, const int* __restrict__ dst, int e) {
    int i = blockIdx.x * blockDim.x + threadIdx.x;
    if (i >= e) return;
    int d = dst[i];
    int pos = atomicAdd(&g_cur[d], 1);
    g_csrc[pos] = src[i];
}

// ---------------- W split+transpose: [64][256] -> hi/lo [mat][256][64] -----
__global__ void k_wsplit(const float* __restrict__ Wl, const float* __restrict__ Wr) {
    int i = blockIdx.x * blockDim.x + threadIdx.x;   // 2*64*256
    if (i >= 2 * 64 * 256) return;
    int mat = i >> 14;
    int rem = i & 16383;
    int k = rem >> 8, nn = rem & 255;
    float w = mat ? Wr[k * 256 + nn] : Wl[k * 256 + nn];
    __nv_bfloat16 hi = __float2bfloat16_rn(w);
    __nv_bfloat16 lo = __float2bfloat16_rn(w - __bfloat162float(hi));
    g_wth[mat * 16384 + nn * HID + k] = hi;
    g_wtl[mat * 16384 + nn * HID + k] = lo;
}

// ---------------- GEMM1: g_xw = x @ W_gcn ----------------------------------
__global__ void k_gemm1(const float* __restrict__ X, const float* __restrict__ W, int n) {
    __shared__ float xs[64 * 68];
    __shared__ float ws[64 * 64];
    int tid = threadIdx.x;
    int tx = tid & 15, ty = tid >> 4;
    int row0 = blockIdx.x * 64;
    float acc[4][4] = {};

    for (int kc = 0; kc < IND; kc += 64) {
        #pragma unroll
        for (int i = 0; i < 4; i++) {
            int li = tid + i * 256;
            int r = li >> 4, k4 = li & 15;
            float4 v = make_float4(0.f, 0.f, 0.f, 0.f);
            if (row0 + r < n)
                v = *(const float4*)&X[(size_t)(row0 + r) * IND + kc + k4 * 4];
            *(float4*)&xs[r * 68 + k4 * 4] = v;
        }
        #pragma unroll
        for (int i = 0; i < 4; i++) {
            int li = tid + i * 256;
            int k = li >> 4, c4 = li & 15;
            *(float4*)&ws[k * 64 + c4 * 4] = *(const float4*)&W[(kc + k) * HID + c4 * 4];
        }
        __syncthreads();
        #pragma unroll 16
        for (int k = 0; k < 64; k++) {
            float4 wv = *(float4*)&ws[k * 64 + tx * 4];
            #pragma unroll
            for (int j = 0; j < 4; j++) {
                float a = xs[(ty * 4 + j) * 68 + k];
                acc[j][0] += a * wv.x; acc[j][1] += a * wv.y;
                acc[j][2] += a * wv.z; acc[j][3] += a * wv.w;
            }
        }
        __syncthreads();
    }
    #pragma unroll
    for (int j = 0; j < 4; j++) {
        int r = row0 + ty * 4 + j;
        if (r < n)
            *(float4*)&g_xw[r * HID + tx * 4] =
                make_float4(acc[j][0], acc[j][1], acc[j][2], acc[j][3]);
    }
}

// ---------------- GCN via CSR: warp per dst node; emits bf16 hi/lo ---------
__global__ void k_gcn(const float* __restrict__ bg, int n) {
    int node = (blockIdx.x * blockDim.x + threadIdx.x) >> 5;
    int lane = threadIdx.x & 31;
    if (node >= n) return;
    int r0 = g_offs[node], r1 = g_offs[node + 1];

    float2 sum = make_float2(0.f, 0.f);
    for (int base = r0; base < r1; base += 32) {
        int rem = r1 - base;
        int cnt = rem < 32 ? rem : 32;
        int sidx = 0; float sw = 0.f;
        if (lane < cnt) { sidx = g_csrc[base + lane]; sw = g_dinv[sidx]; }
        int k = 0;
        for (; k + 1 < cnt; k += 2) {
            int   s0 = __shfl_sync(FULLM, sidx, k);
            int   s1 = __shfl_sync(FULLM, sidx, k + 1);
            float w0 = __shfl_sync(FULLM, sw,   k);
            float w1 = __shfl_sync(FULLM, sw,   k + 1);
            float2 v0 = *(const float2*)&g_xw[(size_t)s0 * HID + lane * 2];
            float2 v1 = *(const float2*)&g_xw[(size_t)s1 * HID + lane * 2];
            sum.x += w0 * v0.x + w1 * v1.x;
            sum.y += w0 * v0.y + w1 * v1.y;
        }
        if (k < cnt) {
            int   s0 = __shfl_sync(FULLM, sidx, k);
            float w0 = __shfl_sync(FULLM, sw,   k);
            float2 v0 = *(const float2*)&g_xw[(size_t)s0 * HID + lane * 2];
            sum.x += w0 * v0.x; sum.y += w0 * v0.y;
        }
    }
    float wd = g_dinv[node];
    float2 sv = *(const float2*)&g_xw[(size_t)node * HID + lane * 2];
    sum.x = (sum.x + wd * sv.x) * wd;
    sum.y = (sum.y + wd * sv.y) * wd;
    float2 bb = *(const float2*)&bg[lane * 2];
    float hx = fmaxf(sum.x + bb.x, 0.f);
    float hy = fmaxf(sum.y + bb.y, 0.f);

    __nv_bfloat16 hix = __float2bfloat16_rn(hx);
    __nv_bfloat16 hiy = __float2bfloat16_rn(hy);
    __nv_bfloat162 hi2; hi2.x = hix; hi2.y = hiy;
    __nv_bfloat162 lo2;
    lo2.x = __float2bfloat16_rn(hx - __bfloat162float(hix));
    lo2.y = __float2bfloat16_rn(hy - __bfloat162float(hiy));
    *(__nv_bfloat162*)&g_hh[(size_t)node * HID + lane * 2] = hi2;
    *(__nv_bfloat162*)&g_hl[(size_t)node * HID + lane * 2] = lo2;
}

// ---------------- GEMM2 via tensor cores (bf16 split, 3-term) --------------
// grid: (ceil(n/64), 2 mats), block 256 = 8 warps.
// warp w: m-tile (w&3)*16, n-half (w>>2)*128; computes 16 rows x 128 cols.
__global__ void k_mma2(const float* __restrict__ bl, const float* __restrict__ br,
                       int n) {
    int tid  = threadIdx.x;
    int lane = tid & 31;
    int warp = tid >> 5;
    int mat  = blockIdx.y;
    int m0   = blockIdx.x * 64 + (warp & 3) * 16;
    int nb   = (warp >> 2) * 128;
    const __nv_bfloat16* wth = g_wth + mat * 16384;
    const __nv_bfloat16* wtl = g_wtl + mat * 16384;
    const float* bias = mat ? br : bl;
    float* OUT = mat ? g_xr : g_xl;

    int g  = lane >> 2;
    int tg = lane & 3;
    int row0 = m0 + g;          // may exceed n; arrays padded, stores guarded
    int row1 = m0 + g + 8;

    float4 C[16];
    #pragma unroll
    for (int t = 0; t < 16; t++) C[t] = make_float4(0.f, 0.f, 0.f, 0.f);

    #pragma unroll
    for (int kc = 0; kc < 4; kc++) {
        int k0 = kc * 16 + tg * 2;
        unsigned ah0 = *(const unsigned*)&g_hh[(size_t)row0 * HID + k0];
        unsigned ah1 = *(const unsigned*)&g_hh[(size_t)row1 * HID + k0];
        unsigned ah2 = *(const unsigned*)&g_hh[(size_t)row0 * HID + k0 + 8];
        unsigned ah3 = *(const unsigned*)&g_hh[(size_t)row1 * HID + k0 + 8];
        unsigned al0 = *(const unsigned*)&g_hl[(size_t)row0 * HID + k0];
        unsigned al1 = *(const unsigned*)&g_hl[(size_t)row1 * HID + k0];
        unsigned al2 = *(const unsigned*)&g_hl[(size_t)row0 * HID + k0 + 8];
        unsigned al3 = *(const unsigned*)&g_hl[(size_t)row1 * HID + k0 + 8];

        #pragma unroll
        for (int nt = 0; nt < 16; nt++) {
            int nn = nb + nt * 8 + g;
            unsigned bh0 = *(const unsigned*)&wth[nn * HID + k0];
            unsigned bh1 = *(const unsigned*)&wth[nn * HID + k0 + 8];
            unsigned bl0 = *(const unsigned*)&wtl[nn * HID + k0];
            unsigned bl1 = *(const unsigned*)&wtl[nn * HID + k0 + 8];
            mma_bf16(C[nt], ah0, ah1, ah2, ah3, bh0, bh1);
            mma_bf16(C[nt], ah0, ah1, ah2, ah3, bl0, bl1);
            mma_bf16(C[nt], al0, al1, al2, al3, bh0, bh1);
        }
    }

    bool v0 = row0 < n, v1 = row1 < n;
    #pragma unroll
    for (int nt = 0; nt < 16; nt++) {
        int c = nb + nt * 8 + tg * 2;
        float2 bv = *(const float2*)&bias[c];
        if (v0) *(float2*)&OUT[(size_t)row0 * 256 + c] =
            make_float2(C[nt].x + bv.x, C[nt].y + bv.y);
        if (v1) *(float2*)&OUT[(size_t)row1 * 256 + c] =
            make_float2(C[nt].z + bv.x, C[nt].w + bv.y);
    }
}

// ---------------- Fused GATv2 + mean + relu + linear: warp per dst node ----
__global__ void k_gat(const float* __restrict__ att, const float* __restrict__ bgat,
                      const float* __restrict__ Wlin, const float* __restrict__ blin,
                      float* __restrict__ out, int n) {
    int node = (blockIdx.x * blockDim.x + threadIdx.x) >> 5;
    int lane = threadIdx.x & 31;
    if (node >= n) return;
    int off = lane * 8;

    float4 at0 = *(const float4*)&att[off];
    float4 at1 = *(const float4*)&att[off + 4];
    float4 xr0 = *(const float4*)&g_xr[(size_t)node * 256 + off];
    float4 xr1 = *(const float4*)&g_xr[(size_t)node * 256 + off + 4];

    float4 a0 = *(const float4*)&g_xl[(size_t)node * 256 + off];
    float4 a1 = *(const float4*)&g_xl[(size_t)node * 256 + off + 4];
    float z = at0.x * lrelu(a0.x + xr0.x) + at0.y * lrelu(a0.y + xr0.y)
            + at0.z * lrelu(a0.z + xr0.z) + at0.w * lrelu(a0.w + xr0.w)
            + at1.x * lrelu(a1.x + xr1.x) + at1.y * lrelu(a1.y + xr1.y)
            + at1.z * lrelu(a1.z + xr1.z) + at1.w * lrelu(a1.w + xr1.w);
    z += __shfl_xor_sync(FULLM, z, 1);
    z += __shfl_xor_sync(FULLM, z, 2);
    z += __shfl_xor_sync(FULLM, z, 4);
    float m = z;
    float den = 1.f;

    int r0 = g_offs[node], r1 = g_offs[node + 1];
    for (int base = r0; base < r1; base += 32) {
        int rem = r1 - base;
        int cnt = rem < 32 ? rem : 32;
        int sidx = (lane < cnt) ? g_csrc[base + lane] : 0;
        int k = 0;
        for (; k + 1 < cnt; k += 2) {
            int s0 = __shfl_sync(FULLM, sidx, k);
            int s1 = __shfl_sync(FULLM, sidx, k + 1);
            float4 u0 = *(const float4*)&g_xl[(size_t)s0 * 256 + off];
            float4 u1 = *(const float4*)&g_xl[(size_t)s0 * 256 + off + 4];
            float4 w0 = *(const float4*)&g_xl[(size_t)s1 * 256 + off];
            float4 w1 = *(const float4*)&g_xl[(size_t)s1 * 256 + off + 4];
            float za = at0.x * lrelu(u0.x + xr0.x) + at0.y * lrelu(u0.y + xr0.y)
                     + at0.z * lrelu(u0.z + xr0.z) + at0.w * lrelu(u0.w + xr0.w)
                     + at1.x * lrelu(u1.x + xr1.x) + at1.y * lrelu(u1.y + xr1.y)
                     + at1.z * lrelu(u1.z + xr1.z) + at1.w * lrelu(u1.w + xr1.w);
            float zb = at0.x * lrelu(w0.x + xr0.x) + at0.y * lrelu(w0.y + xr0.y)
                     + at0.z * lrelu(w0.z + xr0.z) + at0.w * lrelu(w0.w + xr0.w)
                     + at1.x * lrelu(w1.x + xr1.x) + at1.y * lrelu(w1.y + xr1.y)
                     + at1.z * lrelu(w1.z + xr1.z) + at1.w * lrelu(w1.w + xr1.w);
            za += __shfl_xor_sync(FULLM, za, 1);
            zb += __shfl_xor_sync(FULLM, zb, 1);
            za += __shfl_xor_sync(FULLM, za, 2);
            zb += __shfl_xor_sync(FULLM, zb, 2);
            za += __shfl_xor_sync(FULLM, za, 4);
            zb += __shfl_xor_sync(FULLM, zb, 4);

            float mn = fmaxf(m, fmaxf(za, zb));
            float pa = __expf(za - mn);
            float pb = __expf(zb - mn);
            if (mn == m) {
                den += pa + pb;
                a0.x += pa * u0.x + pb * w0.x;  a0.y += pa * u0.y + pb * w0.y;
                a0.z += pa * u0.z + pb * w0.z;  a0.w += pa * u0.w + pb * w0.w;
                a1.x += pa * u1.x + pb * w1.x;  a1.y += pa * u1.y + pb * w1.y;
                a1.z += pa * u1.z + pb * w1.z;  a1.w += pa * u1.w + pb * w1.w;
            } else {
                float sc = __expf(m - mn);
                den = den * sc + pa + pb;
                a0.x = a0.x * sc + pa * u0.x + pb * w0.x;
                a0.y = a0.y * sc + pa * u0.y + pb * w0.y;
                a0.z = a0.z * sc + pa * u0.z + pb * w0.z;
                a0.w = a0.w * sc + pa * u0.w + pb * w0.w;
                a1.x = a1.x * sc + pa * u1.x + pb * w1.x;
                a1.y = a1.y * sc + pa * u1.y + pb * w1.y;
                a1.z = a1.z * sc + pa * u1.z + pb * w1.z;
                a1.w = a1.w * sc + pa * u1.w + pb * w1.w;
                m = mn;
            }
        }
        if (k < cnt) {
            int s0 = __shfl_sync(FULLM, sidx, k);
            float4 u0 = *(const float4*)&g_xl[(size_t)s0 * 256 + off];
            float4 u1 = *(const float4*)&g_xl[(size_t)s0 * 256 + off + 4];
            float za = at0.x * lrelu(u0.x + xr0.x) + at0.y * lrelu(u0.y + xr0.y)
                     + at0.z * lrelu(u0.z + xr0.z) + at0.w * lrelu(u0.w + xr0.w)
                     + at1.x * lrelu(u1.x + xr1.x) + at1.y * lrelu(u1.y + xr1.y)
                     + at1.z * lrelu(u1.z + xr1.z) + at1.w * lrelu(u1.w + xr1.w);
            za += __shfl_xor_sync(FULLM, za, 1);
            za += __shfl_xor_sync(FULLM, za, 2);
            za += __shfl_xor_sync(FULLM, za, 4);
            float mn = fmaxf(m, za);
            float pa = __expf(za - mn);
            if (mn == m) {
                den += pa;
                a0.x += pa * u0.x; a0.y += pa * u0.y; a0.z += pa * u0.z; a0.w += pa * u0.w;
                a1.x += pa * u1.x; a1.y += pa * u1.y; a1.z += pa * u1.z; a1.w += pa * u1.w;
            } else {
                float sc = __expf(m - mn);
                den = den * sc + pa;
                a0.x = a0.x * sc + pa * u0.x; a0.y = a0.y * sc + pa * u0.y;
                a0.z = a0.z * sc + pa * u0.z; a0.w = a0.w * sc + pa * u0.w;
                a1.x = a1.x * sc + pa * u1.x; a1.y = a1.y * sc + pa * u1.y;
                a1.z = a1.z * sc + pa * u1.z; a1.w = a1.w * sc + pa * u1.w;
                m = mn;
            }
        }
    }

    float inv = __frcp_rn(den);
    float v[8] = { a0.x * inv, a0.y * inv, a0.z * inv, a0.w * inv,
                   a1.x * inv, a1.y * inv, a1.z * inv, a1.w * inv };

    #pragma unroll
    for (int k = 0; k < 8; k++) {
        v[k] += __shfl_xor_sync(FULLM, v[k], 8);
        v[k] += __shfl_xor_sync(FULLM, v[k], 16);
    }

    int c = (lane & 7) * 8;
    float sc = 0.f;
    #pragma unroll
    for (int k = 0; k < 8; k++) {
        float hv = fmaxf(0.25f * v[k] + __ldg(&bgat[c + k]), 0.f);
        sc += hv * __ldg(&Wlin[c + k]);
    }
    sc += __shfl_xor_sync(FULLM, sc, 1);
    sc += __shfl_xor_sync(FULLM, sc, 2);
    sc += __shfl_xor_sync(FULLM, sc, 4);
    if (lane == 0) out[node] = sc + __ldg(&blin[0]);
}

// ---------------- launch ----------------
extern "C" void kernel_launch(void* const* d_in, const int* in_sizes, int n_in,
                              void* d_out, int out_size) {
    const float* x    = (const float*)d_in[0];
    const int*   ei   = (const int*)d_in[1];
    const float* Wg   = (const float*)d_in[3];
    const float* bg   = (const float*)d_in[4];
    const float* Wl   = (const float*)d_in[5];
    const float* bl   = (const float*)d_in[6];
    const float* Wr   = (const float*)d_in[7];
    const float* br   = (const float*)d_in[8];
    const float* att  = (const float*)d_in[9];
    const float* bgat = (const float*)d_in[10];
    const float* Wlin = (const float*)d_in[11];
    const float* blin = (const float*)d_in[12];
    float* out = (float*)d_out;

    int n = in_sizes[0] / IND;       // 50000
    int e = in_sizes[1] / 2;         // 800000
    const int* src = ei;
    const int* dst = ei + e;
    int nblk = (n + 1023) / 1024;

    static cudaStream_t s2 = nullptr;
    static cudaEvent_t ev1 = nullptr, ev2 = nullptr;
    if (!s2) {
        cudaStreamCreateWithFlags(&s2, cudaStreamNonBlocking);
        cudaEventCreateWithFlags(&ev1, cudaEventDisableTiming);
        cudaEventCreateWithFlags(&ev2, cudaEventDisableTiming);
    }

    // fork: GEMM1 + W split (independent of CSR) on s2
    cudaEventRecord(ev1, 0);
    cudaStreamWaitEvent(s2, ev1, 0);
    k_gemm1 <<<(n + 63) / 64, 256, 0, s2>>>(x, Wg, n);
    k_wsplit<<<(2 * 64 * 256 + 255) / 256, 256, 0, s2>>>(Wl, Wr);
    cudaEventRecord(ev2, s2);

    // CSR build on stream 0
    k_init <<<(n + 255) / 256, 256>>>(n);
    k_hist <<<(e + 255) / 256, 256>>>(dst, e);
    k_scan1<<<nblk, 1024>>>(n);
    k_scan2<<<1, 64>>>(nblk);
    k_scan3<<<(n + 255) / 256, 256>>>(n, e);
    k_fill <<<(e + 255) / 256, 256>>>(src, dst, e);

    cudaStreamWaitEvent(0, ev2, 0);
    k_gcn  <<<(n * 32 + 255) / 256, 256>>>(bg, n);

    dim3 g2((n + 63) / 64, 2);
    k_mma2 <<<g2, 256>>>(bl, br, n);

    k_gat  <<<(n * 32 + 255) / 256, 256>>>(att, bgat, Wlin, blin, out, n);
}

// round 6
// speedup vs baseline: 1.0591x; 1.0591x over previous
#include <cuda_runtime.h>
#include <cuda_fp16.h>

#define IND   128
#define HID   64
#define HEADS 4
#define NEG   0.2f

#define NMAX  50000
#define EMAX  800000
#define FULLM 0xffffffffu

#define FMA2(d, a, b) asm("fma.rn.f32x2 %0, %1, %2, %0;" : "+l"(d) : "l"(a), "l"(b))
#define UNPK(lo, hi, in) asm("mov.b64 {%0, %1}, %2;" : "=r"(lo), "=r"(hi) : "l"(in))

// ---------------- scratch (device globals; no allocation allowed) ----------
static __device__ int    g_cnt [NMAX];
static __device__ int    g_offs[NMAX + 1];
static __device__ int    g_cur [NMAX];
static __device__ int    g_bsum[512];
static __device__ int    g_csrc[EMAX];
static __device__ float  g_dinv[NMAX];
static __device__ float  g_xw  [NMAX * HID];
static __device__ float  g_h   [NMAX * HID];
static __device__ __half g_xlh [NMAX * HEADS * HID];   // xl in fp16
static __device__ float  g_xr  [NMAX * HEADS * HID];

__device__ __forceinline__ float lrelu(float z) { return z > 0.f ? z : NEG * z; }

// ---------------- CSR build ----------------
__global__ void k_init(int n) {
    int i = blockIdx.x * blockDim.x + threadIdx.x;
    if (i < n) g_cnt[i] = 0;
}

__global__ void k_hist(const int* __restrict__ dst, int e) {
    int i = blockIdx.x * blockDim.x + threadIdx.x;
    if (i < e) atomicAdd(&g_cnt[dst[i]], 1);
}

__global__ void k_scan1(int n) {
    __shared__ int wsum[32];
    int i = blockIdx.x * 1024 + threadIdx.x;
    int v = (i < n) ? g_cnt[i] : 0;
    int lane = threadIdx.x & 31, wid = threadIdx.x >> 5;
    int x = v;
    #pragma unroll
    for (int o = 1; o < 32; o <<= 1) {
        int t = __shfl_up_sync(FULLM, x, o);
        if (lane >= o) x += t;
    }
    if (lane == 31) wsum[wid] = x;
    __syncthreads();
    if (wid == 0) {
        int s = wsum[lane];
        #pragma unroll
        for (int o = 1; o < 32; o <<= 1) {
            int t = __shfl_up_sync(FULLM, s, o);
            if (lane >= o) s += t;
        }
        wsum[lane] = s;
    }
    __syncthreads();
    int add = wid ? wsum[wid - 1] : 0;
    if (i < n) g_offs[i] = add + x - v;
    if (threadIdx.x == 1023) g_bsum[blockIdx.x] = wsum[31];
}

__global__ void k_scan2(int nblk) {
    __shared__ int sh[64];
    int v = (threadIdx.x < nblk) ? g_bsum[threadIdx.x] : 0;
    sh[threadIdx.x] = v;
    __syncthreads();
    #pragma unroll
    for (int o = 1; o < 64; o <<= 1) {
        int t = (threadIdx.x >= o) ? sh[threadIdx.x - o] : 0;
        __syncthreads();
        sh[threadIdx.x] += t;
        __syncthreads();
    }
    if (threadIdx.x < nblk) g_bsum[threadIdx.x] = sh[threadIdx.x] - v;
}

__global__ void k_scan3(int n, int e) {
    int i = blockIdx.x * blockDim.x + threadIdx.x;
    if (i < n) {
        int off = g_offs[i] + g_bsum[i >> 10];
        g_offs[i] = off;
        g_cur[i]  = off;
        g_dinv[i] = rsqrtf((float)g_cnt[i] + 1.0f);
    }
    if (i == 0) g_offs[n] = e;
}

__global__ void k_fill(const int* __restrict__ src, const int* __restrict__ dst, int e) {
    int i = blockIdx.x * blockDim.x + threadIdx.x;
    if (i >= e) return;
    int d = dst[i];
    int pos = atomicAdd(&g_cur[d], 1);
    g_csrc[pos] = src[i];
}

// ---------------- GEMM1: g_xw = x @ W_gcn  (f32x2 inner) -------------------
__global__ void k_gemm1(const float* __restrict__ X, const float* __restrict__ W, int n) {
    __shared__ float2 as2[64 * 64];   // duplicated A pairs, 32 KB
    __shared__ float  ws [64 * 64];   // 16 KB
    int tid = threadIdx.x;
    int tx = tid & 15, ty = tid >> 4;
    int row0 = blockIdx.x * 64;
    unsigned long long acc[4][2] = {};

    for (int kc = 0; kc < IND; kc += 64) {
        #pragma unroll
        for (int i = 0; i < 4; i++) {
            int li = tid + i * 256;
            int r = li >> 4, k4 = li & 15;
            float4 v = make_float4(0.f, 0.f, 0.f, 0.f);
            if (row0 + r < n)
                v = *(const float4*)&X[(size_t)(row0 + r) * IND + kc + k4 * 4];
            *(float4*)&as2[r * 64 + k4 * 4]     = make_float4(v.x, v.x, v.y, v.y);
            *(float4*)&as2[r * 64 + k4 * 4 + 2] = make_float4(v.z, v.z, v.w, v.w);
        }
        #pragma unroll
        for (int i = 0; i < 4; i++) {
            int li = tid + i * 256;
            int k = li >> 4, c4 = li & 15;
            *(float4*)&ws[k * 64 + c4 * 4] = *(const float4*)&W[(kc + k) * HID + c4 * 4];
        }
        __syncthreads();
        #pragma unroll 16
        for (int k = 0; k < 64; k++) {
            ulonglong2 wv = *(ulonglong2*)&ws[k * 64 + tx * 4];
            #pragma unroll
            for (int j = 0; j < 4; j++) {
                unsigned long long a2 = *(unsigned long long*)&as2[(ty * 4 + j) * 64 + k];
                FMA2(acc[j][0], a2, wv.x);
                FMA2(acc[j][1], a2, wv.y);
            }
        }
        __syncthreads();
    }
    #pragma unroll
    for (int j = 0; j < 4; j++) {
        int r = row0 + ty * 4 + j;
        if (r < n) {
            unsigned c0, c1, c2, c3;
            UNPK(c0, c1, acc[j][0]);
            UNPK(c2, c3, acc[j][1]);
            *(float4*)&g_xw[r * HID + tx * 4] =
                make_float4(__uint_as_float(c0), __uint_as_float(c1),
                            __uint_as_float(c2), __uint_as_float(c3));
        }
    }
}

// ---------------- GCN via CSR: warp per dst node ---------------------------
__global__ void k_gcn(const float* __restrict__ bg, int n) {
    int node = (blockIdx.x * blockDim.x + threadIdx.x) >> 5;
    int lane = threadIdx.x & 31;
    if (node >= n) return;
    int r0 = g_offs[node], r1 = g_offs[node + 1];

    float2 sum = make_float2(0.f, 0.f);
    for (int base = r0; base < r1; base += 32) {
        int rem = r1 - base;
        int cnt = rem < 32 ? rem : 32;
        int sidx = 0; float sw = 0.f;
        if (lane < cnt) { sidx = g_csrc[base + lane]; sw = g_dinv[sidx]; }
        int k = 0;
        for (; k + 1 < cnt; k += 2) {
            int   s0 = __shfl_sync(FULLM, sidx, k);
            int   s1 = __shfl_sync(FULLM, sidx, k + 1);
            float w0 = __shfl_sync(FULLM, sw,   k);
            float w1 = __shfl_sync(FULLM, sw,   k + 1);
            float2 v0 = *(const float2*)&g_xw[(size_t)s0 * HID + lane * 2];
            float2 v1 = *(const float2*)&g_xw[(size_t)s1 * HID + lane * 2];
            sum.x += w0 * v0.x + w1 * v1.x;
            sum.y += w0 * v0.y + w1 * v1.y;
        }
        if (k < cnt) {
            int   s0 = __shfl_sync(FULLM, sidx, k);
            float w0 = __shfl_sync(FULLM, sw,   k);
            float2 v0 = *(const float2*)&g_xw[(size_t)s0 * HID + lane * 2];
            sum.x += w0 * v0.x; sum.y += w0 * v0.y;
        }
    }
    float wd = g_dinv[node];
    float2 sv = *(const float2*)&g_xw[(size_t)node * HID + lane * 2];
    sum.x = (sum.x + wd * sv.x) * wd;
    sum.y = (sum.y + wd * sv.y) * wd;
    float2 bb = *(const float2*)&bg[lane * 2];
    float2 h;
    h.x = fmaxf(sum.x + bb.x, 0.f);
    h.y = fmaxf(sum.y + bb.y, 0.f);
    *(float2*)&g_h[(size_t)node * HID + lane * 2] = h;
}

// ---------------- GEMM2: xl/xr = g_h @ W + b  (f32x2; xl stored fp16) ------
__global__ void k_gemm2(const float* __restrict__ Wl, const float* __restrict__ bl,
                        const float* __restrict__ Wr, const float* __restrict__ br,
                        int n) {
    __shared__ float2 as2[64 * 64];
    __shared__ float  ws [64 * 64];
    int tid = threadIdx.x;
    int tx = tid & 15, ty = tid >> 4;
    int row0 = blockIdx.x * 64;
    int mat  = blockIdx.y >> 2;
    int c0   = (blockIdx.y & 3) * 64;
    const float* W = mat ? Wr : Wl;
    const float* b = mat ? br : bl;

    #pragma unroll
    for (int i = 0; i < 4; i++) {
        int li = tid + i * 256;
        int r = li >> 4, k4 = li & 15;
        float4 v = make_float4(0.f, 0.f, 0.f, 0.f);
        if (row0 + r < n)
            v = *(const float4*)&g_h[(size_t)(row0 + r) * HID + k4 * 4];
        *(float4*)&as2[r * 64 + k4 * 4]     = make_float4(v.x, v.x, v.y, v.y);
        *(float4*)&as2[r * 64 + k4 * 4 + 2] = make_float4(v.z, v.z, v.w, v.w);
    }
    #pragma unroll
    for (int i = 0; i < 4; i++) {
        int li = tid + i * 256;
        int k = li >> 4, c4 = li & 15;
        *(float4*)&ws[k * 64 + c4 * 4] = *(const float4*)&W[k * (HEADS * HID) + c0 + c4 * 4];
    }
    __syncthreads();

    unsigned long long acc[4][2] = {};
    #pragma unroll 16
    for (int k = 0; k < 64; k++) {
        ulonglong2 wv = *(ulonglong2*)&ws[k * 64 + tx * 4];
        #pragma unroll
        for (int j = 0; j < 4; j++) {
            unsigned long long a2 = *(unsigned long long*)&as2[(ty * 4 + j) * 64 + k];
            FMA2(acc[j][0], a2, wv.x);
            FMA2(acc[j][1], a2, wv.y);
        }
    }

    float4 bv = *(const float4*)&b[c0 + tx * 4];
    #pragma unroll
    for (int j = 0; j < 4; j++) {
        int r = row0 + ty * 4 + j;
        if (r >= n) continue;
        unsigned u0, u1, u2, u3;
        UNPK(u0, u1, acc[j][0]);
        UNPK(u2, u3, acc[j][1]);
        float v0 = __uint_as_float(u0) + bv.x;
        float v1 = __uint_as_float(u1) + bv.y;
        float v2 = __uint_as_float(u2) + bv.z;
        float v3 = __uint_as_float(u3) + bv.w;
        if (mat) {
            *(float4*)&g_xr[(size_t)r * 256 + c0 + tx * 4] =
                make_float4(v0, v1, v2, v3);
        } else {
            __half2 h01 = __floats2half2_rn(v0, v1);
            __half2 h23 = __floats2half2_rn(v2, v3);
            uint2 packed;
            packed.x = *(unsigned*)&h01;
            packed.y = *(unsigned*)&h23;
            *(uint2*)&g_xlh[(size_t)r * 256 + c0 + tx * 4] = packed;
        }
    }
}

// ---------------- fp16 xl load: 8 elems per lane ---------------------------
__device__ __forceinline__ void ld_xl8(int s, int off, float4& a, float4& b) {
    uint4 r = *(const uint4*)&g_xlh[(size_t)s * 256 + off];
    float2 f0 = __half22float2(*(__half2*)&r.x);
    float2 f1 = __half22float2(*(__half2*)&r.y);
    float2 f2 = __half22float2(*(__half2*)&r.z);
    float2 f3 = __half22float2(*(__half2*)&r.w);
    a = make_float4(f0.x, f0.y, f1.x, f1.y);
    b = make_float4(f2.x, f2.y, f3.x, f3.y);
}

// ---------------- Fused GATv2 + mean + relu + linear: warp per dst node ----
__global__ void k_gat(const float* __restrict__ att, const float* __restrict__ bgat,
                      const float* __restrict__ Wlin, const float* __restrict__ blin,
                      float* __restrict__ out, int n) {
    int node = (blockIdx.x * blockDim.x + threadIdx.x) >> 5;
    int lane = threadIdx.x & 31;
    if (node >= n) return;
    int off = lane * 8;

    float4 at0 = *(const float4*)&att[off];
    float4 at1 = *(const float4*)&att[off + 4];
    float4 xr0 = *(const float4*)&g_xr[(size_t)node * 256 + off];
    float4 xr1 = *(const float4*)&g_xr[(size_t)node * 256 + off + 4];

    float4 a0, a1;
    ld_xl8(node, off, a0, a1);
    float z = at0.x * lrelu(a0.x + xr0.x) + at0.y * lrelu(a0.y + xr0.y)
            + at0.z * lrelu(a0.z + xr0.z) + at0.w * lrelu(a0.w + xr0.w)
            + at1.x * lrelu(a1.x + xr1.x) + at1.y * lrelu(a1.y + xr1.y)
            + at1.z * lrelu(a1.z + xr1.z) + at1.w * lrelu(a1.w + xr1.w);
    z += __shfl_xor_sync(FULLM, z, 1);
    z += __shfl_xor_sync(FULLM, z, 2);
    z += __shfl_xor_sync(FULLM, z, 4);
    float m = z;
    float den = 1.f;

    int r0 = g_offs[node], r1 = g_offs[node + 1];
    for (int base = r0; base < r1; base += 32) {
        int rem = r1 - base;
        int cnt = rem < 32 ? rem : 32;
        int sidx = (lane < cnt) ? g_csrc[base + lane] : 0;
        int k = 0;
        for (; k + 1 < cnt; k += 2) {
            int s0 = __shfl_sync(FULLM, sidx, k);
            int s1 = __shfl_sync(FULLM, sidx, k + 1);
            float4 u0, u1, w0, w1;
            ld_xl8(s0, off, u0, u1);
            ld_xl8(s1, off, w0, w1);
            float za = at0.x * lrelu(u0.x + xr0.x) + at0.y * lrelu(u0.y + xr0.y)
                     + at0.z * lrelu(u0.z + xr0.z) + at0.w * lrelu(u0.w + xr0.w)
                     + at1.x * lrelu(u1.x + xr1.x) + at1.y * lrelu(u1.y + xr1.y)
                     + at1.z * lrelu(u1.z + xr1.z) + at1.w * lrelu(u1.w + xr1.w);
            float zb = at0.x * lrelu(w0.x + xr0.x) + at0.y * lrelu(w0.y + xr0.y)
                     + at0.z * lrelu(w0.z + xr0.z) + at0.w * lrelu(w0.w + xr0.w)
                     + at1.x * lrelu(w1.x + xr1.x) + at1.y * lrelu(w1.y + xr1.y)
                     + at1.z * lrelu(w1.z + xr1.z) + at1.w * lrelu(w1.w + xr1.w);
            za += __shfl_xor_sync(FULLM, za, 1);
            zb += __shfl_xor_sync(FULLM, zb, 1);
            za += __shfl_xor_sync(FULLM, za, 2);
            zb += __shfl_xor_sync(FULLM, zb, 2);
            za += __shfl_xor_sync(FULLM, za, 4);
            zb += __shfl_xor_sync(FULLM, zb, 4);

            float mn = fmaxf(m, fmaxf(za, zb));
            float pa = __expf(za - mn);
            float pb = __expf(zb - mn);
            if (mn == m) {
                den += pa + pb;
                a0.x += pa * u0.x + pb * w0.x;  a0.y += pa * u0.y + pb * w0.y;
                a0.z += pa * u0.z + pb * w0.z;  a0.w += pa * u0.w + pb * w0.w;
                a1.x += pa * u1.x + pb * w1.x;  a1.y += pa * u1.y + pb * w1.y;
                a1.z += pa * u1.z + pb * w1.z;  a1.w += pa * u1.w + pb * w1.w;
            } else {
                float sc = __expf(m - mn);
                den = den * sc + pa + pb;
                a0.x = a0.x * sc + pa * u0.x + pb * w0.x;
                a0.y = a0.y * sc + pa * u0.y + pb * w0.y;
                a0.z = a0.z * sc + pa * u0.z + pb * w0.z;
                a0.w = a0.w * sc + pa * u0.w + pb * w0.w;
                a1.x = a1.x * sc + pa * u1.x + pb * w1.x;
                a1.y = a1.y * sc + pa * u1.y + pb * w1.y;
                a1.z = a1.z * sc + pa * u1.z + pb * w1.z;
                a1.w = a1.w * sc + pa * u1.w + pb * w1.w;
                m = mn;
            }
        }
        if (k < cnt) {
            int s0 = __shfl_sync(FULLM, sidx, k);
            float4 u0, u1;
            ld_xl8(s0, off, u0, u1);
            float za = at0.x * lrelu(u0.x + xr0.x) + at0.y * lrelu(u0.y + xr0.y)
                     + at0.z * lrelu(u0.z + xr0.z) + at0.w * lrelu(u0.w + xr0.w)
                     + at1.x * lrelu(u1.x + xr1.x) + at1.y * lrelu(u1.y + xr1.y)
                     + at1.z * lrelu(u1.z + xr1.z) + at1.w * lrelu(u1.w + xr1.w);
            za += __shfl_xor_sync(FULLM, za, 1);
            za += __shfl_xor_sync(FULLM, za, 2);
            za += __shfl_xor_sync(FULLM, za, 4);
            float mn = fmaxf(m, za);
            float pa = __expf(za - mn);
            if (mn == m) {
                den += pa;
                a0.x += pa * u0.x; a0.y += pa * u0.y; a0.z += pa * u0.z; a0.w += pa * u0.w;
                a1.x += pa * u1.x; a1.y += pa * u1.y; a1.z += pa * u1.z; a1.w += pa * u1.w;
            } else {
                float sc = __expf(m - mn);
                den = den * sc + pa;
                a0.x = a0.x * sc + pa * u0.x; a0.y = a0.y * sc + pa * u0.y;
                a0.z = a0.z * sc + pa * u0.z; a0.w = a0.w * sc + pa * u0.w;
                a1.x = a1.x * sc + pa * u1.x; a1.y = a1.y * sc + pa * u1.y;
                a1.z = a1.z * sc + pa * u1.z; a1.w = a1.w * sc + pa * u1.w;
                m = mn;
            }
        }
    }

    float inv = __frcp_rn(den);
    float v[8] = { a0.x * inv, a0.y * inv, a0.z * inv, a0.w * inv,
                   a1.x * inv, a1.y * inv, a1.z * inv, a1.w * inv };

    #pragma unroll
    for (int k = 0; k < 8; k++) {
        v[k] += __shfl_xor_sync(FULLM, v[k], 8);
        v[k] += __shfl_xor_sync(FULLM, v[k], 16);
    }

    int c = (lane & 7) * 8;
    float sc = 0.f;
    #pragma unroll
    for (int k = 0; k < 8; k++) {
        float hv = fmaxf(0.25f * v[k] + __ldg(&bgat[c + k]), 0.f);
        sc += hv * __ldg(&Wlin[c + k]);
    }
    sc += __shfl_xor_sync(FULLM, sc, 1);
    sc += __shfl_xor_sync(FULLM, sc, 2);
    sc += __shfl_xor_sync(FULLM, sc, 4);
    if (lane == 0) out[node] = sc + __ldg(&blin[0]);
}

// ---------------- launch ----------------
extern "C" void kernel_launch(void* const* d_in, const int* in_sizes, int n_in,
                              void* d_out, int out_size) {
    const float* x    = (const float*)d_in[0];
    const int*   ei   = (const int*)d_in[1];
    const float* Wg   = (const float*)d_in[3];
    const float* bg   = (const float*)d_in[4];
    const float* Wl   = (const float*)d_in[5];
    const float* bl   = (const float*)d_in[6];
    const float* Wr   = (const float*)d_in[7];
    const float* br   = (const float*)d_in[8];
    const float* att  = (const float*)d_in[9];
    const float* bgat = (const float*)d_in[10];
    const float* Wlin = (const float*)d_in[11];
    const float* blin = (const float*)d_in[12];
    float* out = (float*)d_out;

    int n = in_sizes[0] / IND;       // 50000
    int e = in_sizes[1] / 2;         // 800000
    const int* src = ei;
    const int* dst = ei + e;
    int nblk = (n + 1023) / 1024;

    static cudaStream_t s2 = nullptr;
    static cudaEvent_t ev1 = nullptr, ev2 = nullptr;
    if (!s2) {
        cudaStreamCreateWithFlags(&s2, cudaStreamNonBlocking);
        cudaEventCreateWithFlags(&ev1, cudaEventDisableTiming);
        cudaEventCreateWithFlags(&ev2, cudaEventDisableTiming);
    }

    // fork: GEMM1 (independent of CSR) on s2
    cudaEventRecord(ev1, 0);
    cudaStreamWaitEvent(s2, ev1, 0);
    k_gemm1<<<(n + 63) / 64, 256, 0, s2>>>(x, Wg, n);
    cudaEventRecord(ev2, s2);

    // CSR build on stream 0
    k_init <<<(n + 255) / 256, 256>>>(n);
    k_hist <<<(e + 255) / 256, 256>>>(dst, e);
    k_scan1<<<nblk, 1024>>>(n);
    k_scan2<<<1, 64>>>(nblk);
    k_scan3<<<(n + 255) / 256, 256>>>(n, e);
    k_fill <<<(e + 255) / 256, 256>>>(src, dst, e);

    cudaStreamWaitEvent(0, ev2, 0);
    k_gcn  <<<(n * 32 + 255) / 256, 256>>>(bg, n);

    dim3 g2((n + 63) / 64, 8);
    k_gemm2<<<g2, 256>>>(Wl, bl, Wr, br, n);

    k_gat  <<<(n * 32 + 255) / 256, 256>>>(att, bgat, Wlin, blin, out, n);
}

// round 7
// speedup vs baseline: 1.1980x; 1.1312x over previous
#include <cuda_runtime.h>
#include <cuda_fp16.h>

#define IND   128
#define HID   64
#define HEADS 4
#define NEG   0.2f

#define NMAX  50000
#define EMAX  800000
#define FULLM 0xffffffffu

// ---------------- scratch (device globals; no allocation allowed) ----------
static __device__ int    g_cnt [NMAX];
static __device__ int    g_offs[NMAX + 1];
static __device__ int    g_cur [NMAX];
static __device__ int    g_bsum[512];
static __device__ int    g_csrc[EMAX];
static __device__ float  g_dinv[NMAX];
static __device__ float  g_xw  [NMAX * HID];
static __device__ float  g_h   [NMAX * HID];
static __device__ __half g_xlh [NMAX * HEADS * HID];   // xl in fp16
static __device__ float  g_xr  [NMAX * HEADS * HID];

__device__ __forceinline__ float lrelu(float z) { return z > 0.f ? z : NEG * z; }

// ---------------- CSR build ----------------
__global__ void k_init(int n) {
    int i = blockIdx.x * blockDim.x + threadIdx.x;
    if (i < n) g_cnt[i] = 0;
}

__global__ void k_hist(const int* __restrict__ dst, int e) {
    int i = blockIdx.x * blockDim.x + threadIdx.x;
    if (i < e) atomicAdd(&g_cnt[dst[i]], 1);
}

__global__ void k_scan1(int n) {
    __shared__ int wsum[32];
    int i = blockIdx.x * 1024 + threadIdx.x;
    int v = (i < n) ? g_cnt[i] : 0;
    int lane = threadIdx.x & 31, wid = threadIdx.x >> 5;
    int x = v;
    #pragma unroll
    for (int o = 1; o < 32; o <<= 1) {
        int t = __shfl_up_sync(FULLM, x, o);
        if (lane >= o) x += t;
    }
    if (lane == 31) wsum[wid] = x;
    __syncthreads();
    if (wid == 0) {
        int s = wsum[lane];
        #pragma unroll
        for (int o = 1; o < 32; o <<= 1) {
            int t = __shfl_up_sync(FULLM, s, o);
            if (lane >= o) s += t;
        }
        wsum[lane] = s;
    }
    __syncthreads();
    int add = wid ? wsum[wid - 1] : 0;
    if (i < n) g_offs[i] = add + x - v;
    if (threadIdx.x == 1023) g_bsum[blockIdx.x] = wsum[31];
}

__global__ void k_scan2(int nblk) {
    __shared__ int sh[64];
    int v = (threadIdx.x < nblk) ? g_bsum[threadIdx.x] : 0;
    sh[threadIdx.x] = v;
    __syncthreads();
    #pragma unroll
    for (int o = 1; o < 64; o <<= 1) {
        int t = (threadIdx.x >= o) ? sh[threadIdx.x - o] : 0;
        __syncthreads();
        sh[threadIdx.x] += t;
        __syncthreads();
    }
    if (threadIdx.x < nblk) g_bsum[threadIdx.x] = sh[threadIdx.x] - v;
}

__global__ void k_scan3(int n, int e) {
    int i = blockIdx.x * blockDim.x + threadIdx.x;
    if (i < n) {
        int off = g_offs[i] + g_bsum[i >> 10];
        g_offs[i] = off;
        g_cur[i]  = off;
        g_dinv[i] = rsqrtf((float)g_cnt[i] + 1.0f);
    }
    if (i == 0) g_offs[n] = e;
}

__global__ void k_fill(const int* __restrict__ src, const int* __restrict__ dst, int e) {
    int i = blockIdx.x * blockDim.x + threadIdx.x;
    if (i >= e) return;
    int d = dst[i];
    int pos = atomicAdd(&g_cur[d], 1);
    g_csrc[pos] = src[i];
}

// ---------------- GEMM1: g_xw = x @ W_gcn ----------------------------------
__global__ void k_gemm1(const float* __restrict__ X, const float* __restrict__ W, int n) {
    __shared__ float xs[64 * 68];
    __shared__ float ws[64 * 64];
    int tid = threadIdx.x;
    int tx = tid & 15, ty = tid >> 4;
    int row0 = blockIdx.x * 64;
    float acc[4][4] = {};

    for (int kc = 0; kc < IND; kc += 64) {
        #pragma unroll
        for (int i = 0; i < 4; i++) {
            int li = tid + i * 256;
            int r = li >> 4, k4 = li & 15;
            float4 v = make_float4(0.f, 0.f, 0.f, 0.f);
            if (row0 + r < n)
                v = *(const float4*)&X[(size_t)(row0 + r) * IND + kc + k4 * 4];
            *(float4*)&xs[r * 68 + k4 * 4] = v;
        }
        #pragma unroll
        for (int i = 0; i < 4; i++) {
            int li = tid + i * 256;
            int k = li >> 4, c4 = li & 15;
            *(float4*)&ws[k * 64 + c4 * 4] = *(const float4*)&W[(kc + k) * HID + c4 * 4];
        }
        __syncthreads();
        #pragma unroll 16
        for (int k = 0; k < 64; k++) {
            float4 wv = *(float4*)&ws[k * 64 + tx * 4];
            #pragma unroll
            for (int j = 0; j < 4; j++) {
                float a = xs[(ty * 4 + j) * 68 + k];
                acc[j][0] += a * wv.x; acc[j][1] += a * wv.y;
                acc[j][2] += a * wv.z; acc[j][3] += a * wv.w;
            }
        }
        __syncthreads();
    }
    #pragma unroll
    for (int j = 0; j < 4; j++) {
        int r = row0 + ty * 4 + j;
        if (r < n)
            *(float4*)&g_xw[r * HID + tx * 4] =
                make_float4(acc[j][0], acc[j][1], acc[j][2], acc[j][3]);
    }
}

// ---------------- GCN via CSR: warp per dst node ---------------------------
__global__ void k_gcn(const float* __restrict__ bg, int n) {
    int node = (blockIdx.x * blockDim.x + threadIdx.x) >> 5;
    int lane = threadIdx.x & 31;
    if (node >= n) return;
    int r0 = g_offs[node], r1 = g_offs[node + 1];

    float2 sum = make_float2(0.f, 0.f);
    for (int base = r0; base < r1; base += 32) {
        int rem = r1 - base;
        int cnt = rem < 32 ? rem : 32;
        int sidx = 0; float sw = 0.f;
        if (lane < cnt) { sidx = g_csrc[base + lane]; sw = g_dinv[sidx]; }
        int k = 0;
        for (; k + 1 < cnt; k += 2) {
            int   s0 = __shfl_sync(FULLM, sidx, k);
            int   s1 = __shfl_sync(FULLM, sidx, k + 1);
            float w0 = __shfl_sync(FULLM, sw,   k);
            float w1 = __shfl_sync(FULLM, sw,   k + 1);
            float2 v0 = *(const float2*)&g_xw[(size_t)s0 * HID + lane * 2];
            float2 v1 = *(const float2*)&g_xw[(size_t)s1 * HID + lane * 2];
            sum.x += w0 * v0.x + w1 * v1.x;
            sum.y += w0 * v0.y + w1 * v1.y;
        }
        if (k < cnt) {
            int   s0 = __shfl_sync(FULLM, sidx, k);
            float w0 = __shfl_sync(FULLM, sw,   k);
            float2 v0 = *(const float2*)&g_xw[(size_t)s0 * HID + lane * 2];
            sum.x += w0 * v0.x; sum.y += w0 * v0.y;
        }
    }
    float wd = g_dinv[node];
    float2 sv = *(const float2*)&g_xw[(size_t)node * HID + lane * 2];
    sum.x = (sum.x + wd * sv.x) * wd;
    sum.y = (sum.y + wd * sv.y) * wd;
    float2 bb = *(const float2*)&bg[lane * 2];
    float2 h;
    h.x = fmaxf(sum.x + bb.x, 0.f);
    h.y = fmaxf(sum.y + bb.y, 0.f);
    *(float2*)&g_h[(size_t)node * HID + lane * 2] = h;
}

// ---------------- GEMM2: xl/xr = g_h @ W + b  (xl stored fp16) -------------
__global__ void k_gemm2(const float* __restrict__ Wl, const float* __restrict__ bl,
                        const float* __restrict__ Wr, const float* __restrict__ br,
                        int n) {
    __shared__ float as_[64 * 68];
    __shared__ float ws [64 * 64];
    int tid = threadIdx.x;
    int tx = tid & 15, ty = tid >> 4;
    int row0 = blockIdx.x * 64;
    int mat  = blockIdx.y >> 2;
    int c0   = (blockIdx.y & 3) * 64;
    const float* W = mat ? Wr : Wl;
    const float* b = mat ? br : bl;

    #pragma unroll
    for (int i = 0; i < 4; i++) {
        int li = tid + i * 256;
        int r = li >> 4, k4 = li & 15;
        float4 v = make_float4(0.f, 0.f, 0.f, 0.f);
        if (row0 + r < n)
            v = *(const float4*)&g_h[(size_t)(row0 + r) * HID + k4 * 4];
        *(float4*)&as_[r * 68 + k4 * 4] = v;
    }
    #pragma unroll
    for (int i = 0; i < 4; i++) {
        int li = tid + i * 256;
        int k = li >> 4, c4 = li & 15;
        *(float4*)&ws[k * 64 + c4 * 4] = *(const float4*)&W[k * (HEADS * HID) + c0 + c4 * 4];
    }
    __syncthreads();

    float acc[4][4] = {};
    #pragma unroll 16
    for (int k = 0; k < 64; k++) {
        float4 wv = *(float4*)&ws[k * 64 + tx * 4];
        #pragma unroll
        for (int j = 0; j < 4; j++) {
            float a = as_[(ty * 4 + j) * 68 + k];
            acc[j][0] += a * wv.x; acc[j][1] += a * wv.y;
            acc[j][2] += a * wv.z; acc[j][3] += a * wv.w;
        }
    }
    float4 bv = *(const float4*)&b[c0 + tx * 4];
    #pragma unroll
    for (int j = 0; j < 4; j++) {
        int r = row0 + ty * 4 + j;
        if (r >= n) continue;
        float v0 = acc[j][0] + bv.x;
        float v1 = acc[j][1] + bv.y;
        float v2 = acc[j][2] + bv.z;
        float v3 = acc[j][3] + bv.w;
        if (mat) {
            *(float4*)&g_xr[(size_t)r * 256 + c0 + tx * 4] =
                make_float4(v0, v1, v2, v3);
        } else {
            __half2 h01 = __floats2half2_rn(v0, v1);
            __half2 h23 = __floats2half2_rn(v2, v3);
            uint2 packed;
            packed.x = *(unsigned*)&h01;
            packed.y = *(unsigned*)&h23;
            *(uint2*)&g_xlh[(size_t)r * 256 + c0 + tx * 4] = packed;
        }
    }
}

// ---------------- fp16 xl load: 8 elems per lane ---------------------------
__device__ __forceinline__ void ld_xl8(int s, int off, float4& a, float4& b) {
    uint4 r = *(const uint4*)&g_xlh[(size_t)s * 256 + off];
    float2 f0 = __half22float2(*(__half2*)&r.x);
    float2 f1 = __half22float2(*(__half2*)&r.y);
    float2 f2 = __half22float2(*(__half2*)&r.z);
    float2 f3 = __half22float2(*(__half2*)&r.w);
    a = make_float4(f0.x, f0.y, f1.x, f1.y);
    b = make_float4(f2.x, f2.y, f3.x, f3.y);
}

// ---------------- Fused GATv2 + mean + relu + linear: warp per dst node ----
__global__ void k_gat(const float* __restrict__ att, const float* __restrict__ bgat,
                      const float* __restrict__ Wlin, const float* __restrict__ blin,
                      float* __restrict__ out, int n) {
    int node = (blockIdx.x * blockDim.x + threadIdx.x) >> 5;
    int lane = threadIdx.x & 31;
    if (node >= n) return;
    int off = lane * 8;

    float4 at0 = *(const float4*)&att[off];
    float4 at1 = *(const float4*)&att[off + 4];
    float4 xr0 = *(const float4*)&g_xr[(size_t)node * 256 + off];
    float4 xr1 = *(const float4*)&g_xr[(size_t)node * 256 + off + 4];

    float4 a0, a1;
    ld_xl8(node, off, a0, a1);
    float z = at0.x * lrelu(a0.x + xr0.x) + at0.y * lrelu(a0.y + xr0.y)
            + at0.z * lrelu(a0.z + xr0.z) + at0.w * lrelu(a0.w + xr0.w)
            + at1.x * lrelu(a1.x + xr1.x) + at1.y * lrelu(a1.y + xr1.y)
            + at1.z * lrelu(a1.z + xr1.z) + at1.w * lrelu(a1.w + xr1.w);
    z += __shfl_xor_sync(FULLM, z, 1);
    z += __shfl_xor_sync(FULLM, z, 2);
    z += __shfl_xor_sync(FULLM, z, 4);
    float m = z;
    float den = 1.f;

    int r0 = g_offs[node], r1 = g_offs[node + 1];
    for (int base = r0; base < r1; base += 32) {
        int rem = r1 - base;
        int cnt = rem < 32 ? rem : 32;
        int sidx = (lane < cnt) ? g_csrc[base + lane] : 0;
        int k = 0;
        for (; k + 1 < cnt; k += 2) {
            int s0 = __shfl_sync(FULLM, sidx, k);
            int s1 = __shfl_sync(FULLM, sidx, k + 1);
            float4 u0, u1, w0, w1;
            ld_xl8(s0, off, u0, u1);
            ld_xl8(s1, off, w0, w1);
            float za = at0.x * lrelu(u0.x + xr0.x) + at0.y * lrelu(u0.y + xr0.y)
                     + at0.z * lrelu(u0.z + xr0.z) + at0.w * lrelu(u0.w + xr0.w)
                     + at1.x * lrelu(u1.x + xr1.x) + at1.y * lrelu(u1.y + xr1.y)
                     + at1.z * lrelu(u1.z + xr1.z) + at1.w * lrelu(u1.w + xr1.w);
            float zb = at0.x * lrelu(w0.x + xr0.x) + at0.y * lrelu(w0.y + xr0.y)
                     + at0.z * lrelu(w0.z + xr0.z) + at0.w * lrelu(w0.w + xr0.w)
                     + at1.x * lrelu(w1.x + xr1.x) + at1.y * lrelu(w1.y + xr1.y)
                     + at1.z * lrelu(w1.z + xr1.z) + at1.w * lrelu(w1.w + xr1.w);
            za += __shfl_xor_sync(FULLM, za, 1);
            zb += __shfl_xor_sync(FULLM, zb, 1);
            za += __shfl_xor_sync(FULLM, za, 2);
            zb += __shfl_xor_sync(FULLM, zb, 2);
            za += __shfl_xor_sync(FULLM, za, 4);
            zb += __shfl_xor_sync(FULLM, zb, 4);

            float mn = fmaxf(m, fmaxf(za, zb));
            float pa = __expf(za - mn);
            float pb = __expf(zb - mn);
            if (mn == m) {
                den += pa + pb;
                a0.x += pa * u0.x + pb * w0.x;  a0.y += pa * u0.y + pb * w0.y;
                a0.z += pa * u0.z + pb * w0.z;  a0.w += pa * u0.w + pb * w0.w;
                a1.x += pa * u1.x + pb * w1.x;  a1.y += pa * u1.y + pb * w1.y;
                a1.z += pa * u1.z + pb * w1.z;  a1.w += pa * u1.w + pb * w1.w;
            } else {
                float sc = __expf(m - mn);
                den = den * sc + pa + pb;
                a0.x = a0.x * sc + pa * u0.x + pb * w0.x;
                a0.y = a0.y * sc + pa * u0.y + pb * w0.y;
                a0.z = a0.z * sc + pa * u0.z + pb * w0.z;
                a0.w = a0.w * sc + pa * u0.w + pb * w0.w;
                a1.x = a1.x * sc + pa * u1.x + pb * w1.x;
                a1.y = a1.y * sc + pa * u1.y + pb * w1.y;
                a1.z = a1.z * sc + pa * u1.z + pb * w1.z;
                a1.w = a1.w * sc + pa * u1.w + pb * w1.w;
                m = mn;
            }
        }
        if (k < cnt) {
            int s0 = __shfl_sync(FULLM, sidx, k);
            float4 u0, u1;
            ld_xl8(s0, off, u0, u1);
            float za = at0.x * lrelu(u0.x + xr0.x) + at0.y * lrelu(u0.y + xr0.y)
                     + at0.z * lrelu(u0.z + xr0.z) + at0.w * lrelu(u0.w + xr0.w)
                     + at1.x * lrelu(u1.x + xr1.x) + at1.y * lrelu(u1.y + xr1.y)
                     + at1.z * lrelu(u1.z + xr1.z) + at1.w * lrelu(u1.w + xr1.w);
            za += __shfl_xor_sync(FULLM, za, 1);
            za += __shfl_xor_sync(FULLM, za, 2);
            za += __shfl_xor_sync(FULLM, za, 4);
            float mn = fmaxf(m, za);
            float pa = __expf(za - mn);
            if (mn == m) {
                den += pa;
                a0.x += pa * u0.x; a0.y += pa * u0.y; a0.z += pa * u0.z; a0.w += pa * u0.w;
                a1.x += pa * u1.x; a1.y += pa * u1.y; a1.z += pa * u1.z; a1.w += pa * u1.w;
            } else {
                float sc = __expf(m - mn);
                den = den * sc + pa;
                a0.x = a0.x * sc + pa * u0.x; a0.y = a0.y * sc + pa * u0.y;
                a0.z = a0.z * sc + pa * u0.z; a0.w = a0.w * sc + pa * u0.w;
                a1.x = a1.x * sc + pa * u1.x; a1.y = a1.y * sc + pa * u1.y;
                a1.z = a1.z * sc + pa * u1.z; a1.w = a1.w * sc + pa * u1.w;
                m = mn;
            }
        }
    }

    float inv = __frcp_rn(den);
    float v[8] = { a0.x * inv, a0.y * inv, a0.z * inv, a0.w * inv,
                   a1.x * inv, a1.y * inv, a1.z * inv, a1.w * inv };

    #pragma unroll
    for (int k = 0; k < 8; k++) {
        v[k] += __shfl_xor_sync(FULLM, v[k], 8);
        v[k] += __shfl_xor_sync(FULLM, v[k], 16);
    }

    int c = (lane & 7) * 8;
    float sc = 0.f;
    #pragma unroll
    for (int k = 0; k < 8; k++) {
        float hv = fmaxf(0.25f * v[k] + __ldg(&bgat[c + k]), 0.f);
        sc += hv * __ldg(&Wlin[c + k]);
    }
    sc += __shfl_xor_sync(FULLM, sc, 1);
    sc += __shfl_xor_sync(FULLM, sc, 2);
    sc += __shfl_xor_sync(FULLM, sc, 4);
    if (lane == 0) out[node] = sc + __ldg(&blin[0]);
}

// ---------------- launch ----------------
extern "C" void kernel_launch(void* const* d_in, const int* in_sizes, int n_in,
                              void* d_out, int out_size) {
    const float* x    = (const float*)d_in[0];
    const int*   ei   = (const int*)d_in[1];
    const float* Wg   = (const float*)d_in[3];
    const float* bg   = (const float*)d_in[4];
    const float* Wl   = (const float*)d_in[5];
    const float* bl   = (const float*)d_in[6];
    const float* Wr   = (const float*)d_in[7];
    const float* br   = (const float*)d_in[8];
    const float* att  = (const float*)d_in[9];
    const float* bgat = (const float*)d_in[10];
    const float* Wlin = (const float*)d_in[11];
    const float* blin = (const float*)d_in[12];
    float* out = (float*)d_out;

    int n = in_sizes[0] / IND;       // 50000
    int e = in_sizes[1] / 2;         // 800000
    const int* src = ei;
    const int* dst = ei + e;
    int nblk = (n + 1023) / 1024;

    static cudaStream_t s2 = nullptr;
    static cudaEvent_t ev1 = nullptr, ev2 = nullptr;
    if (!s2) {
        cudaStreamCreateWithFlags(&s2, cudaStreamNonBlocking);
        cudaEventCreateWithFlags(&ev1, cudaEventDisableTiming);
        cudaEventCreateWithFlags(&ev2, cudaEventDisableTiming);
    }

    // fork: GEMM1 (independent of CSR) on s2
    cudaEventRecord(ev1, 0);
    cudaStreamWaitEvent(s2, ev1, 0);
    k_gemm1<<<(n + 63) / 64, 256, 0, s2>>>(x, Wg, n);
    cudaEventRecord(ev2, s2);

    // CSR build on stream 0
    k_init <<<(n + 255) / 256, 256>>>(n);
    k_hist <<<(e + 255) / 256, 256>>>(dst, e);
    k_scan1<<<nblk, 1024>>>(n);
    k_scan2<<<1, 64>>>(nblk);
    k_scan3<<<(n + 255) / 256, 256>>>(n, e);
    k_fill <<<(e + 255) / 256, 256>>>(src, dst, e);

    cudaStreamWaitEvent(0, ev2, 0);
    k_gcn  <<<(n * 32 + 255) / 256, 256>>>(bg, n);

    dim3 g2((n + 63) / 64, 8);
    k_gemm2<<<g2, 256>>>(Wl, bl, Wr, br, n);

    k_gat  <<<(n * 32 + 255) / 256, 256>>>(att, bgat, Wlin, blin, out, n);
}